// round 12
// baseline (speedup 1.0000x reference)
#include <cuda_runtime.h>
#include <cstdint>

#define Mm 32768   // B*N points

// ---------------- static device scratch ----------------
__device__ float g_qg[Mm * 64];   // x @ (wq@g1)
__device__ float g_kg[Mm * 64];   // x @ (wk@g1)
__device__ float g_v [Mm * 64];   // x @ wv
__device__ float g_Wd2g1[4096];   // d2 @ g1
__device__ float g_Wqg1[4096];    // wq @ g1
__device__ float g_Wkg1[4096];    // wk @ g1
__device__ float g_cvec[64];      // d2b @ g1 + g1b

// ---------------- f32x2 packed-FMA helpers ----------------
__device__ __forceinline__ unsigned long long pack2(float x, float y) {
    unsigned long long r; asm("mov.b64 %0, {%1, %2};" : "=l"(r) : "f"(x), "f"(y)); return r;
}
__device__ __forceinline__ void fma2(unsigned long long& d, unsigned long long a, unsigned long long b) {
    asm("fma.rn.f32x2 %0, %1, %2, %0;" : "+l"(d) : "l"(a), "l"(b));
}
__device__ __forceinline__ float2 unpk(unsigned long long v) {
    float x, y; asm("mov.b64 {%0, %1}, %2;" : "=f"(x), "=f"(y) : "l"(v)); return make_float2(x, y);
}

// ---------------- 4x4-tile gemm (k0/k1) ----------------
__device__ __forceinline__ void rank1(float a0, float a1, float a2, float a3,
                                      ulonglong2 b, unsigned long long acc[4][2]) {
    unsigned long long t;
    t = pack2(a0, a0); fma2(acc[0][0], t, b.x); fma2(acc[0][1], t, b.y);
    t = pack2(a1, a1); fma2(acc[1][0], t, b.x); fma2(acc[1][1], t, b.y);
    t = pack2(a2, a2); fma2(acc[2][0], t, b.x); fma2(acc[2][1], t, b.y);
    t = pack2(a3, a3); fma2(acc[3][0], t, b.x); fma2(acc[3][1], t, b.y);
}
__device__ __forceinline__ void gemm64(const float* As, const float* Ws,
                                       int r0, int c0, unsigned long long acc[4][2]) {
#pragma unroll
    for (int i = 0; i < 4; i++) { acc[i][0] = 0ULL; acc[i][1] = 0ULL; }
#pragma unroll
    for (int k4 = 0; k4 < 16; ++k4) {
        float4 a0 = *reinterpret_cast<const float4*>(As + (r0 + 0) * 68 + k4 * 4);
        float4 a1 = *reinterpret_cast<const float4*>(As + (r0 + 1) * 68 + k4 * 4);
        float4 a2 = *reinterpret_cast<const float4*>(As + (r0 + 2) * 68 + k4 * 4);
        float4 a3 = *reinterpret_cast<const float4*>(As + (r0 + 3) * 68 + k4 * 4);
        ulonglong2 b0 = *reinterpret_cast<const ulonglong2*>(Ws + (k4 * 4 + 0) * 68 + c0);
        ulonglong2 b1 = *reinterpret_cast<const ulonglong2*>(Ws + (k4 * 4 + 1) * 68 + c0);
        ulonglong2 b2 = *reinterpret_cast<const ulonglong2*>(Ws + (k4 * 4 + 2) * 68 + c0);
        ulonglong2 b3 = *reinterpret_cast<const ulonglong2*>(Ws + (k4 * 4 + 3) * 68 + c0);
        rank1(a0.x, a1.x, a2.x, a3.x, b0, acc);
        rank1(a0.y, a1.y, a2.y, a3.y, b1, acc);
        rank1(a0.z, a1.z, a2.z, a3.z, b2, acc);
        rank1(a0.w, a1.w, a2.w, a3.w, b3, acc);
    }
}
__device__ __forceinline__ void loadW(float* dst, const float* __restrict__ src, int tid) {
#pragma unroll
    for (int e = tid; e < 1024; e += 256) {
        int row = e >> 4, c4 = e & 15;
        float4 v = *reinterpret_cast<const float4*>(src + row * 64 + c4 * 4);
        *reinterpret_cast<float4*>(dst + row * 68 + c4 * 4) = v;
    }
}

// =========================================================================
// k0: weight products (canary kernel — keep identical across rounds)
// =========================================================================
__global__ __launch_bounds__(256)
void k0_prep(const float* __restrict__ d2w, const float* __restrict__ g1w,
             const float* __restrict__ wq, const float* __restrict__ wk,
             const float* __restrict__ d2b, const float* __restrict__ g1b) {
    __shared__ float As[64 * 68];
    __shared__ float Bs[64 * 68];
    const int tid = threadIdx.x, m = blockIdx.x;
    const float* A = (m == 0) ? d2w : (m == 1) ? wq : wk;
    loadW(As, A, tid);
    loadW(Bs, g1w, tid);
    __syncthreads();
    const int r0 = (tid >> 4) * 4, c0 = (tid & 15) * 4;
    unsigned long long acc[4][2];
    gemm64(As, Bs, r0, c0, acc);
    float* dst = (m == 0) ? g_Wd2g1 : (m == 1) ? g_Wqg1 : g_Wkg1;
#pragma unroll
    for (int i = 0; i < 4; i++) {
        float2 u0 = unpk(acc[i][0]), u1 = unpk(acc[i][1]);
        *reinterpret_cast<float4*>(dst + (r0 + i) * 64 + c0) = make_float4(u0.x, u0.y, u1.x, u1.y);
    }
    if (m == 0 && tid < 64) {
        float c = g1b[tid];
#pragma unroll 8
        for (int k = 0; k < 64; k++) c = fmaf(__ldg(&d2b[k]), Bs[k * 68 + tid], c);
        g_cvec[tid] = c;
    }
}

// =========================================================================
// k1: x = features@fc1+b ; qg = x@Wqg1 ; kg = x@Wkg1 ; v = x@wv
// =========================================================================
__global__ __launch_bounds__(256)
void k1_proj(const float* __restrict__ features,
             const float* __restrict__ fc1w, const float* __restrict__ fc1b,
             const float* __restrict__ wv) {
    __shared__ float Fs[64 * 68];
    __shared__ float Ws[64 * 68];
    const int tid = threadIdx.x;
    const int m0 = blockIdx.x * 64;
    const int r0 = (tid >> 4) * 4, c0 = (tid & 15) * 4;

#pragma unroll
    for (int e = tid; e < 1024; e += 256) {
        int row = e >> 4, c4 = e & 15;
        float4 v = *reinterpret_cast<const float4*>(features + (m0 + row) * 64 + c4 * 4);
        *reinterpret_cast<float4*>(Fs + row * 68 + c4 * 4) = v;
    }
    loadW(Ws, fc1w, tid);
    __syncthreads();

    unsigned long long acc[4][2];
    gemm64(Fs, Ws, r0, c0, acc);
    __syncthreads();
#pragma unroll
    for (int i = 0; i < 4; i++) {
        float2 u0 = unpk(acc[i][0]), u1 = unpk(acc[i][1]);
        Fs[(r0 + i) * 68 + c0 + 0] = u0.x + __ldg(&fc1b[c0 + 0]);
        Fs[(r0 + i) * 68 + c0 + 1] = u0.y + __ldg(&fc1b[c0 + 1]);
        Fs[(r0 + i) * 68 + c0 + 2] = u1.x + __ldg(&fc1b[c0 + 2]);
        Fs[(r0 + i) * 68 + c0 + 3] = u1.y + __ldg(&fc1b[c0 + 3]);
    }
    loadW(Ws, (const float*)g_Wqg1, tid);
    __syncthreads();
    gemm64(Fs, Ws, r0, c0, acc);
#pragma unroll
    for (int i = 0; i < 4; i++) {
        float2 u0 = unpk(acc[i][0]), u1 = unpk(acc[i][1]);
        *reinterpret_cast<float4*>(g_qg + (m0 + r0 + i) * 64 + c0) = make_float4(u0.x, u0.y, u1.x, u1.y);
    }
    __syncthreads();
    loadW(Ws, (const float*)g_Wkg1, tid);
    __syncthreads();
    gemm64(Fs, Ws, r0, c0, acc);
#pragma unroll
    for (int i = 0; i < 4; i++) {
        float2 u0 = unpk(acc[i][0]), u1 = unpk(acc[i][1]);
        *reinterpret_cast<float4*>(g_kg + (m0 + r0 + i) * 64 + c0) = make_float4(u0.x, u0.y, u1.x, u1.y);
    }
    __syncthreads();
    loadW(Ws, wv, tid);
    __syncthreads();
    gemm64(Fs, Ws, r0, c0, acc);
#pragma unroll
    for (int i = 0; i < 4; i++) {
        float2 u0 = unpk(acc[i][0]), u1 = unpk(acc[i][1]);
        *reinterpret_cast<float4*>(g_v + (m0 + r0 + i) * 64 + c0) = make_float4(u0.x, u0.y, u1.x, u1.y);
    }
}

// =========================================================================
// k2: 256 thr = 2 groups x 128 thr; group = 64 rows (4 pts x 16 nbrs).
// 4x8 register tiles, 2 CTAs/SM, double-buffered weights. NEW vs R11:
//   - d1 packed as float4(wx,wy,wz,b): T-stage 4 LDS.128/chunk, spread over
//     all 128 threads (2 threads per row)
//   - kg gather prefetched into registers during GEMM2
// =========================================================================
__device__ __forceinline__ void gemmT4(const float* __restrict__ Tb,
                                       const float* __restrict__ W,
                                       int trr, int tcoff, unsigned long long acc[4][4]) {
    const float4* ap0 = reinterpret_cast<const float4*>(Tb + (trr +  0) * 68);
    const float4* ap1 = reinterpret_cast<const float4*>(Tb + (trr + 16) * 68);
    const float4* ap2 = reinterpret_cast<const float4*>(Tb + (trr + 32) * 68);
    const float4* ap3 = reinterpret_cast<const float4*>(Tb + (trr + 48) * 68);
    const ulonglong2* wp = reinterpret_cast<const ulonglong2*>(W + tcoff);
#pragma unroll
    for (int i = 0; i < 4; i++) { acc[i][0] = acc[i][1] = acc[i][2] = acc[i][3] = 0ULL; }
#pragma unroll
    for (int k4 = 0; k4 < 16; k4++) {
        float4 Av[4];
        Av[0] = ap0[k4]; Av[1] = ap1[k4]; Av[2] = ap2[k4]; Av[3] = ap3[k4];
#pragma unroll
        for (int kk = 0; kk < 4; kk++) {
            ulonglong2 b0 = wp[(k4 * 4 + kk) * 17];
            ulonglong2 b1 = wp[(k4 * 4 + kk) * 17 + 1];
#pragma unroll
            for (int i = 0; i < 4; i++) {
                float a = (kk == 0) ? Av[i].x : (kk == 1) ? Av[i].y : (kk == 2) ? Av[i].z : Av[i].w;
                unsigned long long t = pack2(a, a);
                fma2(acc[i][0], t, b0.x); fma2(acc[i][1], t, b0.y);
                fma2(acc[i][2], t, b1.x); fma2(acc[i][3], t, b1.y);
            }
        }
    }
}

// cooperative padded weight load (256 threads): col -> col + 4*(col>=32)
__device__ __forceinline__ void loadWp(float* dst, const float* __restrict__ src, int tid) {
#pragma unroll
    for (int e = tid; e < 1024; e += 256) {
        int row = e >> 4, c4 = e & 15;
        float4 v = __ldg(reinterpret_cast<const float4*>(src + row * 64 + c4 * 4));
        *reinterpret_cast<float4*>(dst + row * 68 + c4 * 4 + ((c4 >> 3) << 2)) = v;
    }
}

__global__ __launch_bounds__(256, 2)
void k2_main(const float* __restrict__ xyz, const float* __restrict__ features,
             const int* __restrict__ knn,
             const float* __restrict__ d1w, const float* __restrict__ d1b,
             const float* __restrict__ d2w, const float* __restrict__ d2b,
             const float* __restrict__ g2w, const float* __restrict__ g2b,
             const float* __restrict__ fc2w, const float* __restrict__ fc2b,
             float* __restrict__ outRes, float* __restrict__ outAttn) {
    extern __shared__ float sm[];
    float* W0    = sm;                     // 4352 (padded cols)
    float* W1    = sm + 4352;              // 4352
    const int tid = threadIdx.x;           // 0..255
    const int g = tid >> 7, l = tid & 127;
    const int tc = l & 7, trr = l >> 3;    // trr 0..15
    float* Tb    = sm + 8704  + g * 4352;  // 64 x stride 68
    float* vpS   = sm + 17408 + g * 4352;  // 64 x stride 68
    float* qgS   = sm + 26112;             // 512
    float* resS  = sm + 26624;             // 512
    int*   growsS = (int*)(sm + 27136);    // 128
    float* d1p   = sm + 27264;             // 64 x float4 = 256
    float* d2bS  = sm + 27520;
    float* cvecS = sm + 27584;
    float* g2bS  = sm + 27648;             // end 27712 floats = 110848 B
    const int pbase = blockIdx.x * 8;

    // ---- setup: both weight buffers resident ----
    loadWp(W0, d2w, tid);
    loadWp(W1, (const float*)g_Wd2g1, tid);
    if (tid < 64) {
        *reinterpret_cast<float4*>(d1p + tid * 4) =
            make_float4(d1w[tid], d1w[64 + tid], d1w[128 + tid], d1b[tid]);
        d2bS[tid] = d2b[tid]; cvecS[tid] = g_cvec[tid]; g2bS[tid] = g2b[tid];
    }
    for (int e = tid; e < 512; e += 256) qgS[e] = g_qg[(pbase + (e >> 6)) * 64 + (e & 63)];

    if (l < 64) {
        const int pi_st = pbase + g * 4 + (l >> 4);
        growsS[g * 64 + l] = ((pi_st >> 13) << 13) | knn[pi_st * 16 + (l & 15)];
    }
    __syncthreads();

    const int c0 = tc * 8;

    // ---- prefetch v-gather into registers (covered by T-stage + GEMM1) ----
    float4 vpre0[4], vpre1[4];
#pragma unroll
    for (int i = 0; i < 4; i++) {
        int grow = growsS[g * 64 + trr + 16 * i];
        vpre0[i] = __ldg(reinterpret_cast<const float4*>(g_v + (size_t)grow * 64 + c0));
        vpre1[i] = __ldg(reinterpret_cast<const float4*>(g_v + (size_t)grow * 64 + c0 + 4));
    }

    // ---- stage T = relu(rel@d1 + d1b): all 128 threads, 2 per row ----
    {
        const int r = l >> 1, h = l & 1;
        const int pi = pbase + g * 4 + (r >> 4);
        const int grow = growsS[g * 64 + r];
        const float rx = xyz[pi * 3 + 0] - xyz[grow * 3 + 0];
        const float ry = xyz[pi * 3 + 1] - xyz[grow * 3 + 1];
        const float rz = xyz[pi * 3 + 2] - xyz[grow * 3 + 2];
#pragma unroll
        for (int cc = 0; cc < 8; cc++) {
            int c4 = h * 8 + cc;
            float v[4];
#pragma unroll
            for (int u = 0; u < 4; u++) {
                float4 w = *reinterpret_cast<const float4*>(d1p + (c4 * 4 + u) * 4);
                v[u] = fmaxf(fmaf(rx, w.x, fmaf(ry, w.y, fmaf(rz, w.z, w.w))), 0.f);
            }
            *reinterpret_cast<float4*>(Tb + r * 68 + c4 * 4) = make_float4(v[0], v[1], v[2], v[3]);
        }
    }
    __syncthreads();

    const int tcoff = tc * 8 + ((tc >> 2) << 2);   // padded col offset
    unsigned long long acc[4][4];
    float2 u0, u1, u2, u3;

    // ---- GEMM1: pos = T@d2 (+d2b); vp = v_prefetch + pos -> vpS ----
    gemmT4(Tb, W0, trr, tcoff, acc);
#pragma unroll
    for (int i = 0; i < 4; i++) {
        int r = trr + 16 * i;
        u0 = unpk(acc[i][0]); u1 = unpk(acc[i][1]); u2 = unpk(acc[i][2]); u3 = unpk(acc[i][3]);
        float4 w0 = make_float4(vpre0[i].x + u0.x + d2bS[c0 + 0], vpre0[i].y + u0.y + d2bS[c0 + 1],
                                vpre0[i].z + u1.x + d2bS[c0 + 2], vpre0[i].w + u1.y + d2bS[c0 + 3]);
        float4 w1 = make_float4(vpre1[i].x + u2.x + d2bS[c0 + 4], vpre1[i].y + u2.y + d2bS[c0 + 5],
                                vpre1[i].z + u3.x + d2bS[c0 + 6], vpre1[i].w + u3.y + d2bS[c0 + 7]);
        *reinterpret_cast<float4*>(vpS + r * 68 + c0)     = w0;
        *reinterpret_cast<float4*>(vpS + r * 68 + c0 + 4) = w1;
    }
    __syncthreads();                 // GEMM1 W0/Tb reads done

    // ---- prefetch kg-gather + stage g2 (latency rides under GEMM2) ----
    float4 kpre0[4], kpre1[4];
#pragma unroll
    for (int i = 0; i < 4; i++) {
        int grow = growsS[g * 64 + trr + 16 * i];
        kpre0[i] = __ldg(reinterpret_cast<const float4*>(g_kg + (size_t)grow * 64 + c0));
        kpre1[i] = __ldg(reinterpret_cast<const float4*>(g_kg + (size_t)grow * 64 + c0 + 4));
    }
    float4 g2r[4];
#pragma unroll
    for (int e2 = 0; e2 < 4; e2++) {
        int e = tid + e2 * 256;
        int row = e >> 4, c4 = e & 15;
        g2r[e2] = __ldg(reinterpret_cast<const float4*>(g2w + row * 64 + c4 * 4));
    }

    // ---- GEMM2: Tg = T@(d2@g1); a1 = relu(Tg + qg - kg + cvec) ----
    gemmT4(Tb, W1, trr, tcoff, acc);
    float a1s[4][8];
#pragma unroll
    for (int i = 0; i < 4; i++) {
        int r = trr + 16 * i;
        int lp = g * 4 + (r >> 4);
        float4 q0 = *reinterpret_cast<const float4*>(qgS + lp * 64 + c0);
        float4 q1 = *reinterpret_cast<const float4*>(qgS + lp * 64 + c0 + 4);
        u0 = unpk(acc[i][0]); u1 = unpk(acc[i][1]); u2 = unpk(acc[i][2]); u3 = unpk(acc[i][3]);
        a1s[i][0] = fmaxf(u0.x + q0.x - kpre0[i].x + cvecS[c0 + 0], 0.f);
        a1s[i][1] = fmaxf(u0.y + q0.y - kpre0[i].y + cvecS[c0 + 1], 0.f);
        a1s[i][2] = fmaxf(u1.x + q0.z - kpre0[i].z + cvecS[c0 + 2], 0.f);
        a1s[i][3] = fmaxf(u1.y + q0.w - kpre0[i].w + cvecS[c0 + 3], 0.f);
        a1s[i][4] = fmaxf(u2.x + q1.x - kpre1[i].x + cvecS[c0 + 4], 0.f);
        a1s[i][5] = fmaxf(u2.y + q1.y - kpre1[i].y + cvecS[c0 + 5], 0.f);
        a1s[i][6] = fmaxf(u3.x + q1.z - kpre1[i].z + cvecS[c0 + 6], 0.f);
        a1s[i][7] = fmaxf(u3.y + q1.w - kpre1[i].w + cvecS[c0 + 7], 0.f);
    }
    __syncthreads();                 // GEMM2 Tb/W1 reads done
    // write a1 -> Tb ; store staged g2 -> W0
#pragma unroll
    for (int i = 0; i < 4; i++) {
        int r = trr + 16 * i;
        *reinterpret_cast<float4*>(Tb + r * 68 + c0)     = make_float4(a1s[i][0], a1s[i][1], a1s[i][2], a1s[i][3]);
        *reinterpret_cast<float4*>(Tb + r * 68 + c0 + 4) = make_float4(a1s[i][4], a1s[i][5], a1s[i][6], a1s[i][7]);
    }
#pragma unroll
    for (int e2 = 0; e2 < 4; e2++) {
        int e = tid + e2 * 256;
        int row = e >> 4, c4 = e & 15;
        *reinterpret_cast<float4*>(W0 + row * 68 + c4 * 4 + ((c4 >> 3) << 2)) = g2r[e2];
    }
    __syncthreads();

    // ---- GEMM3: logits = a1@g2 + g2b ----
    gemmT4(Tb, W0, trr, tcoff, acc);
#pragma unroll
    for (int i = 0; i < 4; i++) {
        u0 = unpk(acc[i][0]); u1 = unpk(acc[i][1]); u2 = unpk(acc[i][2]); u3 = unpk(acc[i][3]);
        a1s[i][0] = u0.x + g2bS[c0 + 0]; a1s[i][1] = u0.y + g2bS[c0 + 1];
        a1s[i][2] = u1.x + g2bS[c0 + 2]; a1s[i][3] = u1.y + g2bS[c0 + 3];
        a1s[i][4] = u2.x + g2bS[c0 + 4]; a1s[i][5] = u2.y + g2bS[c0 + 5];
        a1s[i][6] = u3.x + g2bS[c0 + 6]; a1s[i][7] = u3.y + g2bS[c0 + 7];
    }
    __syncthreads();                 // GEMM3 reads done
#pragma unroll
    for (int i = 0; i < 4; i++) {
        int r = trr + 16 * i;
        *reinterpret_cast<float4*>(Tb + r * 68 + c0)     = make_float4(a1s[i][0], a1s[i][1], a1s[i][2], a1s[i][3]);
        *reinterpret_cast<float4*>(Tb + r * 68 + c0 + 4) = make_float4(a1s[i][4], a1s[i][5], a1s[i][6], a1s[i][7]);
    }
    __syncthreads();

    // ---- softmax over neighbors (axis j) per (point, channel) + res ----
    {
        const int f = l & 63, ph = l >> 6;      // 2 points per thread
#pragma unroll
        for (int it = 0; it < 2; it++) {
            const int p = it * 2 + ph;
            const int pi = pbase + g * 4 + p;
            float z[16], m = -3.402823e38f;
#pragma unroll
            for (int j = 0; j < 16; j++) {
                z[j] = Tb[(p * 16 + j) * 68 + f];
                m = fmaxf(m, z[j]);
            }
            float s = 0.f;
#pragma unroll
            for (int j = 0; j < 16; j++) { float e = __expf((z[j] - m) * 0.125f); z[j] = e; s += e; }
            float inv = 1.f / s, racc = 0.f;
#pragma unroll
            for (int j = 0; j < 16; j++) {
                float a = z[j] * inv;
                outAttn[((size_t)pi * 16 + j) * 64 + f] = a;
                racc = fmaf(a, vpS[(p * 16 + j) * 68 + f], racc);
            }
            resS[(g * 4 + p) * 64 + f] = racc;
        }
    }
    __syncthreads();

    // ---- out = res@fc2 + fc2b + features (2 points per thread) ----
    {
        const int f = l & 63, ph = l >> 6;
        const int p0 = g * 4 + ph * 2;          // two consecutive local points
        float o0 = fc2b[f] + features[(size_t)(pbase + p0 + 0) * 64 + f];
        float o1 = fc2b[f] + features[(size_t)(pbase + p0 + 1) * 64 + f];
#pragma unroll 8
        for (int i = 0; i < 64; i++) {
            float w = __ldg(fc2w + i * 64 + f);
            o0 = fmaf(resS[(p0 + 0) * 64 + i], w, o0);
            o1 = fmaf(resS[(p0 + 1) * 64 + i], w, o1);
        }
        outRes[(size_t)(pbase + p0 + 0) * 64 + f] = o0;
        outRes[(size_t)(pbase + p0 + 1) * 64 + f] = o1;
    }
}

// =========================================================================
extern "C" void kernel_launch(void* const* d_in, const int* in_sizes, int n_in,
                              void* d_out, int out_size) {
    const float* xyz      = (const float*)d_in[0];
    const float* features = (const float*)d_in[1];
    const int*   knn      = (const int*)d_in[2];
    const float* fc1w = (const float*)d_in[3];
    const float* fc1b = (const float*)d_in[4];
    const float* fc2w = (const float*)d_in[5];
    const float* fc2b = (const float*)d_in[6];
    const float* d1w  = (const float*)d_in[7];
    const float* d1b  = (const float*)d_in[8];
    const float* d2w  = (const float*)d_in[9];
    const float* d2b  = (const float*)d_in[10];
    const float* g1w  = (const float*)d_in[11];
    const float* g1b  = (const float*)d_in[12];
    const float* g2w  = (const float*)d_in[13];
    const float* g2b  = (const float*)d_in[14];
    const float* wq   = (const float*)d_in[15];
    const float* wk   = (const float*)d_in[16];
    const float* wv   = (const float*)d_in[17];

    float* outRes  = (float*)d_out;
    float* outAttn = outRes + (size_t)Mm * 64;   // tuple order: (res, attn)

    const int smem2 = 27712 * 4;   // 110848 B -> 2 CTAs/SM
    cudaFuncSetAttribute(k2_main, cudaFuncAttributeMaxDynamicSharedMemorySize, smem2);

    k0_prep<<<3, 256>>>(d2w, g1w, wq, wk, d2b, g1b);
    k1_proj<<<Mm / 64, 256>>>(features, fc1w, fc1b, wv);
    k2_main<<<Mm / 8, 256, smem2>>>(xyz, features, knn,
                                    d1w, d1b, d2w, d2b, g2w, g2b,
                                    fc2w, fc2b, outRes, outAttn);
}

// round 13
// speedup vs baseline: 1.0016x; 1.0016x over previous
#include <cuda_runtime.h>
#include <cstdint>

#define Mm 32768   // B*N points

// ---------------- static device scratch ----------------
__device__ float g_qg[Mm * 64];   // x @ (wq@g1)
__device__ float g_kg[Mm * 64];   // x @ (wk@g1)
__device__ float g_v [Mm * 64];   // x @ wv
__device__ float g_Wd2g1[4096];   // d2 @ g1
__device__ float g_Wqg1[4096];    // wq @ g1
__device__ float g_Wkg1[4096];    // wk @ g1
__device__ float g_cvec[64];      // d2b @ g1 + g1b

#define BARG(id) asm volatile("bar.sync %0, 128;" :: "r"(id) : "memory")

// ---------------- f32x2 packed-FMA helpers ----------------
__device__ __forceinline__ unsigned long long pack2(float x, float y) {
    unsigned long long r; asm("mov.b64 %0, {%1, %2};" : "=l"(r) : "f"(x), "f"(y)); return r;
}
__device__ __forceinline__ void fma2(unsigned long long& d, unsigned long long a, unsigned long long b) {
    asm("fma.rn.f32x2 %0, %1, %2, %0;" : "+l"(d) : "l"(a), "l"(b));
}
__device__ __forceinline__ float2 unpk(unsigned long long v) {
    float x, y; asm("mov.b64 {%0, %1}, %2;" : "=f"(x), "=f"(y) : "l"(v)); return make_float2(x, y);
}

// ---------------- 4x4-tile gemm (k0/k1) ----------------
__device__ __forceinline__ void rank1(float a0, float a1, float a2, float a3,
                                      ulonglong2 b, unsigned long long acc[4][2]) {
    unsigned long long t;
    t = pack2(a0, a0); fma2(acc[0][0], t, b.x); fma2(acc[0][1], t, b.y);
    t = pack2(a1, a1); fma2(acc[1][0], t, b.x); fma2(acc[1][1], t, b.y);
    t = pack2(a2, a2); fma2(acc[2][0], t, b.x); fma2(acc[2][1], t, b.y);
    t = pack2(a3, a3); fma2(acc[3][0], t, b.x); fma2(acc[3][1], t, b.y);
}
__device__ __forceinline__ void gemm64(const float* As, const float* Ws,
                                       int r0, int c0, unsigned long long acc[4][2]) {
#pragma unroll
    for (int i = 0; i < 4; i++) { acc[i][0] = 0ULL; acc[i][1] = 0ULL; }
#pragma unroll
    for (int k4 = 0; k4 < 16; ++k4) {
        float4 a0 = *reinterpret_cast<const float4*>(As + (r0 + 0) * 68 + k4 * 4);
        float4 a1 = *reinterpret_cast<const float4*>(As + (r0 + 1) * 68 + k4 * 4);
        float4 a2 = *reinterpret_cast<const float4*>(As + (r0 + 2) * 68 + k4 * 4);
        float4 a3 = *reinterpret_cast<const float4*>(As + (r0 + 3) * 68 + k4 * 4);
        ulonglong2 b0 = *reinterpret_cast<const ulonglong2*>(Ws + (k4 * 4 + 0) * 68 + c0);
        ulonglong2 b1 = *reinterpret_cast<const ulonglong2*>(Ws + (k4 * 4 + 1) * 68 + c0);
        ulonglong2 b2 = *reinterpret_cast<const ulonglong2*>(Ws + (k4 * 4 + 2) * 68 + c0);
        ulonglong2 b3 = *reinterpret_cast<const ulonglong2*>(Ws + (k4 * 4 + 3) * 68 + c0);
        rank1(a0.x, a1.x, a2.x, a3.x, b0, acc);
        rank1(a0.y, a1.y, a2.y, a3.y, b1, acc);
        rank1(a0.z, a1.z, a2.z, a3.z, b2, acc);
        rank1(a0.w, a1.w, a2.w, a3.w, b3, acc);
    }
}
__device__ __forceinline__ void loadW(float* dst, const float* __restrict__ src, int tid) {
#pragma unroll
    for (int e = tid; e < 1024; e += 256) {
        int row = e >> 4, c4 = e & 15;
        float4 v = *reinterpret_cast<const float4*>(src + row * 64 + c4 * 4);
        *reinterpret_cast<float4*>(dst + row * 68 + c4 * 4) = v;
    }
}

// =========================================================================
// k0: weight products (canary kernel — keep identical across rounds)
// =========================================================================
__global__ __launch_bounds__(256)
void k0_prep(const float* __restrict__ d2w, const float* __restrict__ g1w,
             const float* __restrict__ wq, const float* __restrict__ wk,
             const float* __restrict__ d2b, const float* __restrict__ g1b) {
    __shared__ float As[64 * 68];
    __shared__ float Bs[64 * 68];
    const int tid = threadIdx.x, m = blockIdx.x;
    const float* A = (m == 0) ? d2w : (m == 1) ? wq : wk;
    loadW(As, A, tid);
    loadW(Bs, g1w, tid);
    __syncthreads();
    const int r0 = (tid >> 4) * 4, c0 = (tid & 15) * 4;
    unsigned long long acc[4][2];
    gemm64(As, Bs, r0, c0, acc);
    float* dst = (m == 0) ? g_Wd2g1 : (m == 1) ? g_Wqg1 : g_Wkg1;
#pragma unroll
    for (int i = 0; i < 4; i++) {
        float2 u0 = unpk(acc[i][0]), u1 = unpk(acc[i][1]);
        *reinterpret_cast<float4*>(dst + (r0 + i) * 64 + c0) = make_float4(u0.x, u0.y, u1.x, u1.y);
    }
    if (m == 0 && tid < 64) {
        float c = g1b[tid];
#pragma unroll 8
        for (int k = 0; k < 64; k++) c = fmaf(__ldg(&d2b[k]), Bs[k * 68 + tid], c);
        g_cvec[tid] = c;
    }
}

// =========================================================================
// k1: x = features@fc1+b ; qg = x@Wqg1 ; kg = x@Wkg1 ; v = x@wv
// =========================================================================
__global__ __launch_bounds__(256)
void k1_proj(const float* __restrict__ features,
             const float* __restrict__ fc1w, const float* __restrict__ fc1b,
             const float* __restrict__ wv) {
    __shared__ float Fs[64 * 68];
    __shared__ float Ws[64 * 68];
    const int tid = threadIdx.x;
    const int m0 = blockIdx.x * 64;
    const int r0 = (tid >> 4) * 4, c0 = (tid & 15) * 4;

#pragma unroll
    for (int e = tid; e < 1024; e += 256) {
        int row = e >> 4, c4 = e & 15;
        float4 v = *reinterpret_cast<const float4*>(features + (m0 + row) * 64 + c4 * 4);
        *reinterpret_cast<float4*>(Fs + row * 68 + c4 * 4) = v;
    }
    loadW(Ws, fc1w, tid);
    __syncthreads();

    unsigned long long acc[4][2];
    gemm64(Fs, Ws, r0, c0, acc);
    __syncthreads();
#pragma unroll
    for (int i = 0; i < 4; i++) {
        float2 u0 = unpk(acc[i][0]), u1 = unpk(acc[i][1]);
        Fs[(r0 + i) * 68 + c0 + 0] = u0.x + __ldg(&fc1b[c0 + 0]);
        Fs[(r0 + i) * 68 + c0 + 1] = u0.y + __ldg(&fc1b[c0 + 1]);
        Fs[(r0 + i) * 68 + c0 + 2] = u1.x + __ldg(&fc1b[c0 + 2]);
        Fs[(r0 + i) * 68 + c0 + 3] = u1.y + __ldg(&fc1b[c0 + 3]);
    }
    loadW(Ws, (const float*)g_Wqg1, tid);
    __syncthreads();
    gemm64(Fs, Ws, r0, c0, acc);
#pragma unroll
    for (int i = 0; i < 4; i++) {
        float2 u0 = unpk(acc[i][0]), u1 = unpk(acc[i][1]);
        *reinterpret_cast<float4*>(g_qg + (m0 + r0 + i) * 64 + c0) = make_float4(u0.x, u0.y, u1.x, u1.y);
    }
    __syncthreads();
    loadW(Ws, (const float*)g_Wkg1, tid);
    __syncthreads();
    gemm64(Fs, Ws, r0, c0, acc);
#pragma unroll
    for (int i = 0; i < 4; i++) {
        float2 u0 = unpk(acc[i][0]), u1 = unpk(acc[i][1]);
        *reinterpret_cast<float4*>(g_kg + (m0 + r0 + i) * 64 + c0) = make_float4(u0.x, u0.y, u1.x, u1.y);
    }
    __syncthreads();
    loadW(Ws, wv, tid);
    __syncthreads();
    gemm64(Fs, Ws, r0, c0, acc);
#pragma unroll
    for (int i = 0; i < 4; i++) {
        float2 u0 = unpk(acc[i][0]), u1 = unpk(acc[i][1]);
        *reinterpret_cast<float4*>(g_v + (m0 + r0 + i) * 64 + c0) = make_float4(u0.x, u0.y, u1.x, u1.y);
    }
}

// =========================================================================
// k2: 256 thr = 2 groups x 128 thr; group = 64 rows (4 pts x 16 nbrs).
// 4x8 register tiles, 2 CTAs/SM, double-buffered weights. NEW vs R12:
//   - per-group named barriers (groups drift => epilogue/fma overlap);
//     only the g2->W0 swap uses CTA-wide __syncthreads
//   - softmax remapped to (point, channel-pair): all LDS/STG are 8-byte
// =========================================================================
__device__ __forceinline__ void gemmT4(const float* __restrict__ Tb,
                                       const float* __restrict__ W,
                                       int trr, int tcoff, unsigned long long acc[4][4]) {
    const float4* ap0 = reinterpret_cast<const float4*>(Tb + (trr +  0) * 68);
    const float4* ap1 = reinterpret_cast<const float4*>(Tb + (trr + 16) * 68);
    const float4* ap2 = reinterpret_cast<const float4*>(Tb + (trr + 32) * 68);
    const float4* ap3 = reinterpret_cast<const float4*>(Tb + (trr + 48) * 68);
    const ulonglong2* wp = reinterpret_cast<const ulonglong2*>(W + tcoff);
#pragma unroll
    for (int i = 0; i < 4; i++) { acc[i][0] = acc[i][1] = acc[i][2] = acc[i][3] = 0ULL; }
#pragma unroll
    for (int k4 = 0; k4 < 16; k4++) {
        float4 Av[4];
        Av[0] = ap0[k4]; Av[1] = ap1[k4]; Av[2] = ap2[k4]; Av[3] = ap3[k4];
#pragma unroll
        for (int kk = 0; kk < 4; kk++) {
            ulonglong2 b0 = wp[(k4 * 4 + kk) * 17];
            ulonglong2 b1 = wp[(k4 * 4 + kk) * 17 + 1];
#pragma unroll
            for (int i = 0; i < 4; i++) {
                float a = (kk == 0) ? Av[i].x : (kk == 1) ? Av[i].y : (kk == 2) ? Av[i].z : Av[i].w;
                unsigned long long t = pack2(a, a);
                fma2(acc[i][0], t, b0.x); fma2(acc[i][1], t, b0.y);
                fma2(acc[i][2], t, b1.x); fma2(acc[i][3], t, b1.y);
            }
        }
    }
}

// cooperative padded weight load (256 threads): col -> col + 4*(col>=32)
__device__ __forceinline__ void loadWp(float* dst, const float* __restrict__ src, int tid) {
#pragma unroll
    for (int e = tid; e < 1024; e += 256) {
        int row = e >> 4, c4 = e & 15;
        float4 v = __ldg(reinterpret_cast<const float4*>(src + row * 64 + c4 * 4));
        *reinterpret_cast<float4*>(dst + row * 68 + c4 * 4 + ((c4 >> 3) << 2)) = v;
    }
}

__global__ __launch_bounds__(256, 2)
void k2_main(const float* __restrict__ xyz, const float* __restrict__ features,
             const int* __restrict__ knn,
             const float* __restrict__ d1w, const float* __restrict__ d1b,
             const float* __restrict__ d2w, const float* __restrict__ d2b,
             const float* __restrict__ g2w, const float* __restrict__ g2b,
             const float* __restrict__ fc2w, const float* __restrict__ fc2b,
             float* __restrict__ outRes, float* __restrict__ outAttn) {
    extern __shared__ float sm[];
    float* W0    = sm;                     // 4352 (padded cols)
    float* W1    = sm + 4352;              // 4352
    const int tid = threadIdx.x;           // 0..255
    const int g = tid >> 7, l = tid & 127;
    const int tc = l & 7, trr = l >> 3;    // trr 0..15
    const int gbar = 1 + g;                // named barrier id for this group
    float* Tb    = sm + 8704  + g * 4352;  // 64 x stride 68 (group-private)
    float* vpS   = sm + 17408 + g * 4352;  // 64 x stride 68 (group-private)
    float* qgS   = sm + 26112;             // 512
    float* resS  = sm + 26624;             // 512
    int*   growsS = (int*)(sm + 27136);    // 128
    float* d1p   = sm + 27264;             // 64 x float4 = 256
    float* d2bS  = sm + 27520;
    float* cvecS = sm + 27584;
    float* g2bS  = sm + 27648;             // end 27712 floats = 110848 B
    const int pbase = blockIdx.x * 8;

    // ---- setup: both weight buffers resident ----
    loadWp(W0, d2w, tid);
    loadWp(W1, (const float*)g_Wd2g1, tid);
    if (tid < 64) {
        *reinterpret_cast<float4*>(d1p + tid * 4) =
            make_float4(d1w[tid], d1w[64 + tid], d1w[128 + tid], d1b[tid]);
        d2bS[tid] = d2b[tid]; cvecS[tid] = g_cvec[tid]; g2bS[tid] = g2b[tid];
    }
    for (int e = tid; e < 512; e += 256) qgS[e] = g_qg[(pbase + (e >> 6)) * 64 + (e & 63)];

    if (l < 64) {
        const int pi_st = pbase + g * 4 + (l >> 4);
        growsS[g * 64 + l] = ((pi_st >> 13) << 13) | knn[pi_st * 16 + (l & 15)];
    }
    __syncthreads();

    const int c0 = tc * 8;

    // ---- prefetch v-gather into registers (covered by T-stage + GEMM1) ----
    float4 vpre0[4], vpre1[4];
#pragma unroll
    for (int i = 0; i < 4; i++) {
        int grow = growsS[g * 64 + trr + 16 * i];
        vpre0[i] = __ldg(reinterpret_cast<const float4*>(g_v + (size_t)grow * 64 + c0));
        vpre1[i] = __ldg(reinterpret_cast<const float4*>(g_v + (size_t)grow * 64 + c0 + 4));
    }

    // ---- stage T = relu(rel@d1 + d1b): all 128 group threads, 2 per row ----
    {
        const int r = l >> 1, h = l & 1;
        const int pi = pbase + g * 4 + (r >> 4);
        const int grow = growsS[g * 64 + r];
        const float rx = xyz[pi * 3 + 0] - xyz[grow * 3 + 0];
        const float ry = xyz[pi * 3 + 1] - xyz[grow * 3 + 1];
        const float rz = xyz[pi * 3 + 2] - xyz[grow * 3 + 2];
#pragma unroll
        for (int cc = 0; cc < 8; cc++) {
            int c4 = h * 8 + cc;
            float v[4];
#pragma unroll
            for (int u = 0; u < 4; u++) {
                float4 w = *reinterpret_cast<const float4*>(d1p + (c4 * 4 + u) * 4);
                v[u] = fmaxf(fmaf(rx, w.x, fmaf(ry, w.y, fmaf(rz, w.z, w.w))), 0.f);
            }
            *reinterpret_cast<float4*>(Tb + r * 68 + c4 * 4) = make_float4(v[0], v[1], v[2], v[3]);
        }
    }
    BARG(gbar);                      // group-local: Tb staged

    const int tcoff = tc * 8 + ((tc >> 2) << 2);   // padded col offset
    unsigned long long acc[4][4];
    float2 u0, u1, u2, u3;

    // ---- GEMM1: pos = T@d2 (+d2b); vp = v_prefetch + pos -> vpS ----
    gemmT4(Tb, W0, trr, tcoff, acc);
#pragma unroll
    for (int i = 0; i < 4; i++) {
        int r = trr + 16 * i;
        u0 = unpk(acc[i][0]); u1 = unpk(acc[i][1]); u2 = unpk(acc[i][2]); u3 = unpk(acc[i][3]);
        float4 w0 = make_float4(vpre0[i].x + u0.x + d2bS[c0 + 0], vpre0[i].y + u0.y + d2bS[c0 + 1],
                                vpre0[i].z + u1.x + d2bS[c0 + 2], vpre0[i].w + u1.y + d2bS[c0 + 3]);
        float4 w1 = make_float4(vpre1[i].x + u2.x + d2bS[c0 + 4], vpre1[i].y + u2.y + d2bS[c0 + 5],
                                vpre1[i].z + u3.x + d2bS[c0 + 6], vpre1[i].w + u3.y + d2bS[c0 + 7]);
        *reinterpret_cast<float4*>(vpS + r * 68 + c0)     = w0;
        *reinterpret_cast<float4*>(vpS + r * 68 + c0 + 4) = w1;
    }
    // no barrier: GEMM2 reads only Tb/W1; vpS is group-private and read later

    // ---- prefetch kg-gather + stage g2 (latency rides under GEMM2) ----
    float4 kpre0[4], kpre1[4];
#pragma unroll
    for (int i = 0; i < 4; i++) {
        int grow = growsS[g * 64 + trr + 16 * i];
        kpre0[i] = __ldg(reinterpret_cast<const float4*>(g_kg + (size_t)grow * 64 + c0));
        kpre1[i] = __ldg(reinterpret_cast<const float4*>(g_kg + (size_t)grow * 64 + c0 + 4));
    }
    float4 g2r[4];
#pragma unroll
    for (int e2 = 0; e2 < 4; e2++) {
        int e = tid + e2 * 256;
        int row = e >> 4, c4 = e & 15;
        g2r[e2] = __ldg(reinterpret_cast<const float4*>(g2w + row * 64 + c4 * 4));
    }

    // ---- GEMM2: Tg = T@(d2@g1); a1 = relu(Tg + qg - kg + cvec) ----
    gemmT4(Tb, W1, trr, tcoff, acc);
    float a1s[4][8];
#pragma unroll
    for (int i = 0; i < 4; i++) {
        int r = trr + 16 * i;
        int lp = g * 4 + (r >> 4);
        float4 q0 = *reinterpret_cast<const float4*>(qgS + lp * 64 + c0);
        float4 q1 = *reinterpret_cast<const float4*>(qgS + lp * 64 + c0 + 4);
        u0 = unpk(acc[i][0]); u1 = unpk(acc[i][1]); u2 = unpk(acc[i][2]); u3 = unpk(acc[i][3]);
        a1s[i][0] = fmaxf(u0.x + q0.x - kpre0[i].x + cvecS[c0 + 0], 0.f);
        a1s[i][1] = fmaxf(u0.y + q0.y - kpre0[i].y + cvecS[c0 + 1], 0.f);
        a1s[i][2] = fmaxf(u1.x + q0.z - kpre0[i].z + cvecS[c0 + 2], 0.f);
        a1s[i][3] = fmaxf(u1.y + q0.w - kpre0[i].w + cvecS[c0 + 3], 0.f);
        a1s[i][4] = fmaxf(u2.x + q1.x - kpre1[i].x + cvecS[c0 + 4], 0.f);
        a1s[i][5] = fmaxf(u2.y + q1.y - kpre1[i].y + cvecS[c0 + 5], 0.f);
        a1s[i][6] = fmaxf(u3.x + q1.z - kpre1[i].z + cvecS[c0 + 6], 0.f);
        a1s[i][7] = fmaxf(u3.y + q1.w - kpre1[i].w + cvecS[c0 + 7], 0.f);
    }
    BARG(gbar);                      // group-local: Tb readers (GEMM1/2) done
#pragma unroll
    for (int i = 0; i < 4; i++) {
        int r = trr + 16 * i;
        *reinterpret_cast<float4*>(Tb + r * 68 + c0)     = make_float4(a1s[i][0], a1s[i][1], a1s[i][2], a1s[i][3]);
        *reinterpret_cast<float4*>(Tb + r * 68 + c0 + 4) = make_float4(a1s[i][4], a1s[i][5], a1s[i][6], a1s[i][7]);
    }
    __syncthreads();                 // CTA-wide: both groups past GEMM1 (W0 free)
#pragma unroll
    for (int e2 = 0; e2 < 4; e2++) {
        int e = tid + e2 * 256;
        int row = e >> 4, c4 = e & 15;
        *reinterpret_cast<float4*>(W0 + row * 68 + c4 * 4 + ((c4 >> 3) << 2)) = g2r[e2];
    }
    __syncthreads();                 // CTA-wide: g2 visible

    // ---- GEMM3: logits = a1@g2 + g2b ----
    gemmT4(Tb, W0, trr, tcoff, acc);
#pragma unroll
    for (int i = 0; i < 4; i++) {
        u0 = unpk(acc[i][0]); u1 = unpk(acc[i][1]); u2 = unpk(acc[i][2]); u3 = unpk(acc[i][3]);
        a1s[i][0] = u0.x + g2bS[c0 + 0]; a1s[i][1] = u0.y + g2bS[c0 + 1];
        a1s[i][2] = u1.x + g2bS[c0 + 2]; a1s[i][3] = u1.y + g2bS[c0 + 3];
        a1s[i][4] = u2.x + g2bS[c0 + 4]; a1s[i][5] = u2.y + g2bS[c0 + 5];
        a1s[i][6] = u3.x + g2bS[c0 + 6]; a1s[i][7] = u3.y + g2bS[c0 + 7];
    }
    BARG(gbar);                      // group-local: GEMM3 Tb reads done
#pragma unroll
    for (int i = 0; i < 4; i++) {
        int r = trr + 16 * i;
        *reinterpret_cast<float4*>(Tb + r * 68 + c0)     = make_float4(a1s[i][0], a1s[i][1], a1s[i][2], a1s[i][3]);
        *reinterpret_cast<float4*>(Tb + r * 68 + c0 + 4) = make_float4(a1s[i][4], a1s[i][5], a1s[i][6], a1s[i][7]);
    }
    BARG(gbar);                      // group-local: logits staged

    // ---- softmax over neighbors per (point, channel-pair): 8-byte LDS/STG ----
    {
        const int p = l >> 5;                   // 0..3 (point within group)
        const int f0 = (l & 31) * 2;            // channel pair
        const int pi = pbase + g * 4 + p;
        float2 z[16];
        float m0 = -3.402823e38f, m1 = -3.402823e38f;
#pragma unroll
        for (int j = 0; j < 16; j++) {
            z[j] = *reinterpret_cast<const float2*>(Tb + (p * 16 + j) * 68 + f0);
            m0 = fmaxf(m0, z[j].x); m1 = fmaxf(m1, z[j].y);
        }
        float s0 = 0.f, s1 = 0.f;
#pragma unroll
        for (int j = 0; j < 16; j++) {
            float e0 = __expf((z[j].x - m0) * 0.125f);
            float e1 = __expf((z[j].y - m1) * 0.125f);
            z[j].x = e0; z[j].y = e1; s0 += e0; s1 += e1;
        }
        float inv0 = 1.f / s0, inv1 = 1.f / s1;
        float r0a = 0.f, r1a = 0.f;
#pragma unroll
        for (int j = 0; j < 16; j++) {
            float a0 = z[j].x * inv0, a1 = z[j].y * inv1;
            *reinterpret_cast<float2*>(outAttn + ((size_t)pi * 16 + j) * 64 + f0) = make_float2(a0, a1);
            float2 vp = *reinterpret_cast<const float2*>(vpS + (p * 16 + j) * 68 + f0);
            r0a = fmaf(a0, vp.x, r0a); r1a = fmaf(a1, vp.y, r1a);
        }
        *reinterpret_cast<float2*>(resS + (g * 4 + p) * 64 + f0) = make_float2(r0a, r1a);
    }
    BARG(gbar);                      // group-local: resS staged

    // ---- out = res@fc2 + fc2b + features (2 points per thread) ----
    {
        const int f = l & 63, ph = l >> 6;
        const int p0 = g * 4 + ph * 2;          // two consecutive local points
        float o0 = fc2b[f] + features[(size_t)(pbase + p0 + 0) * 64 + f];
        float o1 = fc2b[f] + features[(size_t)(pbase + p0 + 1) * 64 + f];
#pragma unroll 8
        for (int i = 0; i < 64; i++) {
            float w = __ldg(fc2w + i * 64 + f);
            o0 = fmaf(resS[(p0 + 0) * 64 + i], w, o0);
            o1 = fmaf(resS[(p0 + 1) * 64 + i], w, o1);
        }
        outRes[(size_t)(pbase + p0 + 0) * 64 + f] = o0;
        outRes[(size_t)(pbase + p0 + 1) * 64 + f] = o1;
    }
}

// =========================================================================
extern "C" void kernel_launch(void* const* d_in, const int* in_sizes, int n_in,
                              void* d_out, int out_size) {
    const float* xyz      = (const float*)d_in[0];
    const float* features = (const float*)d_in[1];
    const int*   knn      = (const int*)d_in[2];
    const float* fc1w = (const float*)d_in[3];
    const float* fc1b = (const float*)d_in[4];
    const float* fc2w = (const float*)d_in[5];
    const float* fc2b = (const float*)d_in[6];
    const float* d1w  = (const float*)d_in[7];
    const float* d1b  = (const float*)d_in[8];
    const float* d2w  = (const float*)d_in[9];
    const float* d2b  = (const float*)d_in[10];
    const float* g1w  = (const float*)d_in[11];
    const float* g1b  = (const float*)d_in[12];
    const float* g2w  = (const float*)d_in[13];
    const float* g2b  = (const float*)d_in[14];
    const float* wq   = (const float*)d_in[15];
    const float* wk   = (const float*)d_in[16];
    const float* wv   = (const float*)d_in[17];

    float* outRes  = (float*)d_out;
    float* outAttn = outRes + (size_t)Mm * 64;   // tuple order: (res, attn)

    const int smem2 = 27712 * 4;   // 110848 B -> 2 CTAs/SM
    cudaFuncSetAttribute(k2_main, cudaFuncAttributeMaxDynamicSharedMemorySize, smem2);

    k0_prep<<<3, 256>>>(d2w, g1w, wq, wk, d2b, g1b);
    k1_proj<<<Mm / 64, 256>>>(features, fc1w, fc1b, wv);
    k2_main<<<Mm / 8, 256, smem2>>>(xyz, features, knn,
                                    d1w, d1b, d2w, d2b, g2w, g2b,
                                    fc2w, fc2b, outRes, outAttn);
}

// round 14
// speedup vs baseline: 1.0081x; 1.0065x over previous
#include <cuda_runtime.h>
#include <cstdint>

#define Mm 32768   // B*N points

// ---------------- static device scratch ----------------
__device__ float g_qg[Mm * 64];   // x @ (wq@g1)
__device__ float g_kg[Mm * 64];   // x @ (wk@g1)
__device__ float g_v [Mm * 64];   // x @ wv
__device__ float g_Wd2g1[4096];   // d2 @ g1
__device__ float g_Wqg1[4096];    // wq @ g1
__device__ float g_Wkg1[4096];    // wk @ g1
__device__ float g_cvec[64];      // d2b @ g1 + g1b

#define BARG(id) asm volatile("bar.sync %0, 128;" :: "r"(id) : "memory")

// ---------------- f32x2 packed-FMA helpers ----------------
__device__ __forceinline__ unsigned long long pack2(float x, float y) {
    unsigned long long r; asm("mov.b64 %0, {%1, %2};" : "=l"(r) : "f"(x), "f"(y)); return r;
}
__device__ __forceinline__ void fma2(unsigned long long& d, unsigned long long a, unsigned long long b) {
    asm("fma.rn.f32x2 %0, %1, %2, %0;" : "+l"(d) : "l"(a), "l"(b));
}
__device__ __forceinline__ float2 unpk(unsigned long long v) {
    float x, y; asm("mov.b64 {%0, %1}, %2;" : "=f"(x), "=f"(y) : "l"(v)); return make_float2(x, y);
}

// ---------------- 4x4-tile gemm (k0/k1) ----------------
__device__ __forceinline__ void rank1(float a0, float a1, float a2, float a3,
                                      ulonglong2 b, unsigned long long acc[4][2]) {
    unsigned long long t;
    t = pack2(a0, a0); fma2(acc[0][0], t, b.x); fma2(acc[0][1], t, b.y);
    t = pack2(a1, a1); fma2(acc[1][0], t, b.x); fma2(acc[1][1], t, b.y);
    t = pack2(a2, a2); fma2(acc[2][0], t, b.x); fma2(acc[2][1], t, b.y);
    t = pack2(a3, a3); fma2(acc[3][0], t, b.x); fma2(acc[3][1], t, b.y);
}
__device__ __forceinline__ void gemm64(const float* As, const float* Ws,
                                       int r0, int c0, unsigned long long acc[4][2]) {
#pragma unroll
    for (int i = 0; i < 4; i++) { acc[i][0] = 0ULL; acc[i][1] = 0ULL; }
#pragma unroll
    for (int k4 = 0; k4 < 16; ++k4) {
        float4 a0 = *reinterpret_cast<const float4*>(As + (r0 + 0) * 68 + k4 * 4);
        float4 a1 = *reinterpret_cast<const float4*>(As + (r0 + 1) * 68 + k4 * 4);
        float4 a2 = *reinterpret_cast<const float4*>(As + (r0 + 2) * 68 + k4 * 4);
        float4 a3 = *reinterpret_cast<const float4*>(As + (r0 + 3) * 68 + k4 * 4);
        ulonglong2 b0 = *reinterpret_cast<const ulonglong2*>(Ws + (k4 * 4 + 0) * 68 + c0);
        ulonglong2 b1 = *reinterpret_cast<const ulonglong2*>(Ws + (k4 * 4 + 1) * 68 + c0);
        ulonglong2 b2 = *reinterpret_cast<const ulonglong2*>(Ws + (k4 * 4 + 2) * 68 + c0);
        ulonglong2 b3 = *reinterpret_cast<const ulonglong2*>(Ws + (k4 * 4 + 3) * 68 + c0);
        rank1(a0.x, a1.x, a2.x, a3.x, b0, acc);
        rank1(a0.y, a1.y, a2.y, a3.y, b1, acc);
        rank1(a0.z, a1.z, a2.z, a3.z, b2, acc);
        rank1(a0.w, a1.w, a2.w, a3.w, b3, acc);
    }
}
__device__ __forceinline__ void loadW(float* dst, const float* __restrict__ src, int tid) {
#pragma unroll
    for (int e = tid; e < 1024; e += 256) {
        int row = e >> 4, c4 = e & 15;
        float4 v = *reinterpret_cast<const float4*>(src + row * 64 + c4 * 4);
        *reinterpret_cast<float4*>(dst + row * 68 + c4 * 4) = v;
    }
}

// =========================================================================
// k0: weight products (canary kernel — keep identical across rounds)
// =========================================================================
__global__ __launch_bounds__(256)
void k0_prep(const float* __restrict__ d2w, const float* __restrict__ g1w,
             const float* __restrict__ wq, const float* __restrict__ wk,
             const float* __restrict__ d2b, const float* __restrict__ g1b) {
    __shared__ float As[64 * 68];
    __shared__ float Bs[64 * 68];
    const int tid = threadIdx.x, m = blockIdx.x;
    const float* A = (m == 0) ? d2w : (m == 1) ? wq : wk;
    loadW(As, A, tid);
    loadW(Bs, g1w, tid);
    __syncthreads();
    const int r0 = (tid >> 4) * 4, c0 = (tid & 15) * 4;
    unsigned long long acc[4][2];
    gemm64(As, Bs, r0, c0, acc);
    float* dst = (m == 0) ? g_Wd2g1 : (m == 1) ? g_Wqg1 : g_Wkg1;
#pragma unroll
    for (int i = 0; i < 4; i++) {
        float2 u0 = unpk(acc[i][0]), u1 = unpk(acc[i][1]);
        *reinterpret_cast<float4*>(dst + (r0 + i) * 64 + c0) = make_float4(u0.x, u0.y, u1.x, u1.y);
    }
    if (m == 0 && tid < 64) {
        float c = g1b[tid];
#pragma unroll 8
        for (int k = 0; k < 64; k++) c = fmaf(__ldg(&d2b[k]), Bs[k * 68 + tid], c);
        g_cvec[tid] = c;
    }
}

// =========================================================================
// k1: x = features@fc1+b ; qg = x@Wqg1 ; kg = x@Wkg1 ; v = x@wv
// =========================================================================
__global__ __launch_bounds__(256)
void k1_proj(const float* __restrict__ features,
             const float* __restrict__ fc1w, const float* __restrict__ fc1b,
             const float* __restrict__ wv) {
    __shared__ float Fs[64 * 68];
    __shared__ float Ws[64 * 68];
    const int tid = threadIdx.x;
    const int m0 = blockIdx.x * 64;
    const int r0 = (tid >> 4) * 4, c0 = (tid & 15) * 4;

#pragma unroll
    for (int e = tid; e < 1024; e += 256) {
        int row = e >> 4, c4 = e & 15;
        float4 v = *reinterpret_cast<const float4*>(features + (m0 + row) * 64 + c4 * 4);
        *reinterpret_cast<float4*>(Fs + row * 68 + c4 * 4) = v;
    }
    loadW(Ws, fc1w, tid);
    __syncthreads();

    unsigned long long acc[4][2];
    gemm64(Fs, Ws, r0, c0, acc);
    __syncthreads();
#pragma unroll
    for (int i = 0; i < 4; i++) {
        float2 u0 = unpk(acc[i][0]), u1 = unpk(acc[i][1]);
        Fs[(r0 + i) * 68 + c0 + 0] = u0.x + __ldg(&fc1b[c0 + 0]);
        Fs[(r0 + i) * 68 + c0 + 1] = u0.y + __ldg(&fc1b[c0 + 1]);
        Fs[(r0 + i) * 68 + c0 + 2] = u1.x + __ldg(&fc1b[c0 + 2]);
        Fs[(r0 + i) * 68 + c0 + 3] = u1.y + __ldg(&fc1b[c0 + 3]);
    }
    loadW(Ws, (const float*)g_Wqg1, tid);
    __syncthreads();
    gemm64(Fs, Ws, r0, c0, acc);
#pragma unroll
    for (int i = 0; i < 4; i++) {
        float2 u0 = unpk(acc[i][0]), u1 = unpk(acc[i][1]);
        *reinterpret_cast<float4*>(g_qg + (m0 + r0 + i) * 64 + c0) = make_float4(u0.x, u0.y, u1.x, u1.y);
    }
    __syncthreads();
    loadW(Ws, (const float*)g_Wkg1, tid);
    __syncthreads();
    gemm64(Fs, Ws, r0, c0, acc);
#pragma unroll
    for (int i = 0; i < 4; i++) {
        float2 u0 = unpk(acc[i][0]), u1 = unpk(acc[i][1]);
        *reinterpret_cast<float4*>(g_kg + (m0 + r0 + i) * 64 + c0) = make_float4(u0.x, u0.y, u1.x, u1.y);
    }
    __syncthreads();
    loadW(Ws, wv, tid);
    __syncthreads();
    gemm64(Fs, Ws, r0, c0, acc);
#pragma unroll
    for (int i = 0; i < 4; i++) {
        float2 u0 = unpk(acc[i][0]), u1 = unpk(acc[i][1]);
        *reinterpret_cast<float4*>(g_v + (m0 + r0 + i) * 64 + c0) = make_float4(u0.x, u0.y, u1.x, u1.y);
    }
}

// =========================================================================
// k2: 256 thr = 2 groups x 128 thr; group = 64 rows (4 pts x 16 nbrs).
// NEW vs R13: GEMM1+GEMM2 merged into one 64x128 pass (shared A loads,
// shared pack2); fc2 weights staged into W1 smem (LDS not LDG).
// =========================================================================
__device__ __forceinline__ void gemmT4x2(const float* __restrict__ Tb,
                                         const float* __restrict__ W0,
                                         const float* __restrict__ W1,
                                         int trr, int tcoff,
                                         unsigned long long accA[4][4],
                                         unsigned long long accB[4][4]) {
    const float4* ap0 = reinterpret_cast<const float4*>(Tb + (trr +  0) * 68);
    const float4* ap1 = reinterpret_cast<const float4*>(Tb + (trr + 16) * 68);
    const float4* ap2 = reinterpret_cast<const float4*>(Tb + (trr + 32) * 68);
    const float4* ap3 = reinterpret_cast<const float4*>(Tb + (trr + 48) * 68);
    const ulonglong2* wp0 = reinterpret_cast<const ulonglong2*>(W0 + tcoff);
    const ulonglong2* wp1 = reinterpret_cast<const ulonglong2*>(W1 + tcoff);
#pragma unroll
    for (int i = 0; i < 4; i++) {
        accA[i][0] = accA[i][1] = accA[i][2] = accA[i][3] = 0ULL;
        accB[i][0] = accB[i][1] = accB[i][2] = accB[i][3] = 0ULL;
    }
#pragma unroll
    for (int k4 = 0; k4 < 16; k4++) {
        float4 Av[4];
        Av[0] = ap0[k4]; Av[1] = ap1[k4]; Av[2] = ap2[k4]; Av[3] = ap3[k4];
#pragma unroll
        for (int kk = 0; kk < 4; kk++) {
            ulonglong2 b0 = wp0[(k4 * 4 + kk) * 17];
            ulonglong2 b1 = wp0[(k4 * 4 + kk) * 17 + 1];
            ulonglong2 c0v = wp1[(k4 * 4 + kk) * 17];
            ulonglong2 c1v = wp1[(k4 * 4 + kk) * 17 + 1];
#pragma unroll
            for (int i = 0; i < 4; i++) {
                float a = (kk == 0) ? Av[i].x : (kk == 1) ? Av[i].y : (kk == 2) ? Av[i].z : Av[i].w;
                unsigned long long t = pack2(a, a);
                fma2(accA[i][0], t, b0.x);  fma2(accA[i][1], t, b0.y);
                fma2(accA[i][2], t, b1.x);  fma2(accA[i][3], t, b1.y);
                fma2(accB[i][0], t, c0v.x); fma2(accB[i][1], t, c0v.y);
                fma2(accB[i][2], t, c1v.x); fma2(accB[i][3], t, c1v.y);
            }
        }
    }
}

__device__ __forceinline__ void gemmT4(const float* __restrict__ Tb,
                                       const float* __restrict__ W,
                                       int trr, int tcoff, unsigned long long acc[4][4]) {
    const float4* ap0 = reinterpret_cast<const float4*>(Tb + (trr +  0) * 68);
    const float4* ap1 = reinterpret_cast<const float4*>(Tb + (trr + 16) * 68);
    const float4* ap2 = reinterpret_cast<const float4*>(Tb + (trr + 32) * 68);
    const float4* ap3 = reinterpret_cast<const float4*>(Tb + (trr + 48) * 68);
    const ulonglong2* wp = reinterpret_cast<const ulonglong2*>(W + tcoff);
#pragma unroll
    for (int i = 0; i < 4; i++) { acc[i][0] = acc[i][1] = acc[i][2] = acc[i][3] = 0ULL; }
#pragma unroll
    for (int k4 = 0; k4 < 16; k4++) {
        float4 Av[4];
        Av[0] = ap0[k4]; Av[1] = ap1[k4]; Av[2] = ap2[k4]; Av[3] = ap3[k4];
#pragma unroll
        for (int kk = 0; kk < 4; kk++) {
            ulonglong2 b0 = wp[(k4 * 4 + kk) * 17];
            ulonglong2 b1 = wp[(k4 * 4 + kk) * 17 + 1];
#pragma unroll
            for (int i = 0; i < 4; i++) {
                float a = (kk == 0) ? Av[i].x : (kk == 1) ? Av[i].y : (kk == 2) ? Av[i].z : Av[i].w;
                unsigned long long t = pack2(a, a);
                fma2(acc[i][0], t, b0.x); fma2(acc[i][1], t, b0.y);
                fma2(acc[i][2], t, b1.x); fma2(acc[i][3], t, b1.y);
            }
        }
    }
}

// cooperative padded weight load (256 threads): col -> col + 4*(col>=32)
__device__ __forceinline__ void loadWp(float* dst, const float* __restrict__ src, int tid) {
#pragma unroll
    for (int e = tid; e < 1024; e += 256) {
        int row = e >> 4, c4 = e & 15;
        float4 v = __ldg(reinterpret_cast<const float4*>(src + row * 64 + c4 * 4));
        *reinterpret_cast<float4*>(dst + row * 68 + c4 * 4 + ((c4 >> 3) << 2)) = v;
    }
}

__global__ __launch_bounds__(256, 2)
void k2_main(const float* __restrict__ xyz, const float* __restrict__ features,
             const int* __restrict__ knn,
             const float* __restrict__ d1w, const float* __restrict__ d1b,
             const float* __restrict__ d2w, const float* __restrict__ d2b,
             const float* __restrict__ g2w, const float* __restrict__ g2b,
             const float* __restrict__ fc2w, const float* __restrict__ fc2b,
             float* __restrict__ outRes, float* __restrict__ outAttn) {
    extern __shared__ float sm[];
    float* W0    = sm;                     // 4352 (padded cols)
    float* W1    = sm + 4352;              // 4352
    const int tid = threadIdx.x;           // 0..255
    const int g = tid >> 7, l = tid & 127;
    const int tc = l & 7, trr = l >> 3;    // trr 0..15
    const int gbar = 1 + g;                // named barrier id for this group
    float* Tb    = sm + 8704  + g * 4352;  // 64 x stride 68 (group-private)
    float* vpS   = sm + 17408 + g * 4352;  // 64 x stride 68 (group-private)
    float* qgS   = sm + 26112;             // 512
    float* resS  = sm + 26624;             // 512
    int*   growsS = (int*)(sm + 27136);    // 128
    float* d1p   = sm + 27264;             // 64 x float4 = 256
    float* d2bS  = sm + 27520;
    float* cvecS = sm + 27584;
    float* g2bS  = sm + 27648;             // end 27712 floats = 110848 B
    const int pbase = blockIdx.x * 8;

    // ---- setup: both weight buffers resident ----
    loadWp(W0, d2w, tid);
    loadWp(W1, (const float*)g_Wd2g1, tid);
    if (tid < 64) {
        *reinterpret_cast<float4*>(d1p + tid * 4) =
            make_float4(d1w[tid], d1w[64 + tid], d1w[128 + tid], d1b[tid]);
        d2bS[tid] = d2b[tid]; cvecS[tid] = g_cvec[tid]; g2bS[tid] = g2b[tid];
    }
    for (int e = tid; e < 512; e += 256) qgS[e] = g_qg[(pbase + (e >> 6)) * 64 + (e & 63)];

    if (l < 64) {
        const int pi_st = pbase + g * 4 + (l >> 4);
        growsS[g * 64 + l] = ((pi_st >> 13) << 13) | knn[pi_st * 16 + (l & 15)];
    }
    __syncthreads();

    const int c0 = tc * 8;

    // ---- stage T = relu(rel@d1 + d1b): all 128 group threads, 2 per row ----
    {
        const int r = l >> 1, h = l & 1;
        const int pi = pbase + g * 4 + (r >> 4);
        const int grow = growsS[g * 64 + r];
        const float rx = xyz[pi * 3 + 0] - xyz[grow * 3 + 0];
        const float ry = xyz[pi * 3 + 1] - xyz[grow * 3 + 1];
        const float rz = xyz[pi * 3 + 2] - xyz[grow * 3 + 2];
#pragma unroll
        for (int cc = 0; cc < 8; cc++) {
            int c4 = h * 8 + cc;
            float v[4];
#pragma unroll
            for (int u = 0; u < 4; u++) {
                float4 w = *reinterpret_cast<const float4*>(d1p + (c4 * 4 + u) * 4);
                v[u] = fmaxf(fmaf(rx, w.x, fmaf(ry, w.y, fmaf(rz, w.z, w.w))), 0.f);
            }
            *reinterpret_cast<float4*>(Tb + r * 68 + c4 * 4) = make_float4(v[0], v[1], v[2], v[3]);
        }
    }
    BARG(gbar);                      // group-local: Tb staged

    const int tcoff = tc * 8 + ((tc >> 2) << 2);   // padded col offset
    unsigned long long accA[4][4], accB[4][4];
    float2 u0, u1, u2, u3;

    // ---- merged GEMM1+2: pos = T@d2 ; Tg = T@(d2@g1) ----
    gemmT4x2(Tb, W0, W1, trr, tcoff, accA, accB);

    // ---- epilogue: issue all gathers, then fold ----
    float4 vv0[4], vv1[4], kp0[4], kp1[4];
#pragma unroll
    for (int i = 0; i < 4; i++) {
        int grow = growsS[g * 64 + trr + 16 * i];
        vv0[i] = __ldg(reinterpret_cast<const float4*>(g_v  + (size_t)grow * 64 + c0));
        vv1[i] = __ldg(reinterpret_cast<const float4*>(g_v  + (size_t)grow * 64 + c0 + 4));
        kp0[i] = __ldg(reinterpret_cast<const float4*>(g_kg + (size_t)grow * 64 + c0));
        kp1[i] = __ldg(reinterpret_cast<const float4*>(g_kg + (size_t)grow * 64 + c0 + 4));
    }
    float a1s[4][8];
#pragma unroll
    for (int i = 0; i < 4; i++) {
        int r = trr + 16 * i;
        int lp = g * 4 + (r >> 4);
        // vp = v + pos + d2b
        u0 = unpk(accA[i][0]); u1 = unpk(accA[i][1]); u2 = unpk(accA[i][2]); u3 = unpk(accA[i][3]);
        float4 w0 = make_float4(vv0[i].x + u0.x + d2bS[c0 + 0], vv0[i].y + u0.y + d2bS[c0 + 1],
                                vv0[i].z + u1.x + d2bS[c0 + 2], vv0[i].w + u1.y + d2bS[c0 + 3]);
        float4 w1 = make_float4(vv1[i].x + u2.x + d2bS[c0 + 4], vv1[i].y + u2.y + d2bS[c0 + 5],
                                vv1[i].z + u3.x + d2bS[c0 + 6], vv1[i].w + u3.y + d2bS[c0 + 7]);
        *reinterpret_cast<float4*>(vpS + r * 68 + c0)     = w0;
        *reinterpret_cast<float4*>(vpS + r * 68 + c0 + 4) = w1;
        // a1 = relu(Tg + qg - kg + cvec)
        float4 q0 = *reinterpret_cast<const float4*>(qgS + lp * 64 + c0);
        float4 q1 = *reinterpret_cast<const float4*>(qgS + lp * 64 + c0 + 4);
        u0 = unpk(accB[i][0]); u1 = unpk(accB[i][1]); u2 = unpk(accB[i][2]); u3 = unpk(accB[i][3]);
        a1s[i][0] = fmaxf(u0.x + q0.x - kp0[i].x + cvecS[c0 + 0], 0.f);
        a1s[i][1] = fmaxf(u0.y + q0.y - kp0[i].y + cvecS[c0 + 1], 0.f);
        a1s[i][2] = fmaxf(u1.x + q0.z - kp0[i].z + cvecS[c0 + 2], 0.f);
        a1s[i][3] = fmaxf(u1.y + q0.w - kp0[i].w + cvecS[c0 + 3], 0.f);
        a1s[i][4] = fmaxf(u2.x + q1.x - kp1[i].x + cvecS[c0 + 4], 0.f);
        a1s[i][5] = fmaxf(u2.y + q1.y - kp1[i].y + cvecS[c0 + 5], 0.f);
        a1s[i][6] = fmaxf(u3.x + q1.z - kp1[i].z + cvecS[c0 + 6], 0.f);
        a1s[i][7] = fmaxf(u3.y + q1.w - kp1[i].w + cvecS[c0 + 7], 0.f);
    }
    BARG(gbar);                      // group-local: Tb readers done
#pragma unroll
    for (int i = 0; i < 4; i++) {
        int r = trr + 16 * i;
        *reinterpret_cast<float4*>(Tb + r * 68 + c0)     = make_float4(a1s[i][0], a1s[i][1], a1s[i][2], a1s[i][3]);
        *reinterpret_cast<float4*>(Tb + r * 68 + c0 + 4) = make_float4(a1s[i][4], a1s[i][5], a1s[i][6], a1s[i][7]);
    }

    // ---- stage g2 + fc2w through registers ----
    float4 g2r[4], fc2r[4];
#pragma unroll
    for (int e2 = 0; e2 < 4; e2++) {
        int e = tid + e2 * 256;
        int row = e >> 4, c4 = e & 15;
        g2r[e2]  = __ldg(reinterpret_cast<const float4*>(g2w  + row * 64 + c4 * 4));
        fc2r[e2] = __ldg(reinterpret_cast<const float4*>(fc2w + row * 64 + c4 * 4));
    }
    __syncthreads();                 // CTA-wide: both groups past merged GEMM (W0/W1 free)
#pragma unroll
    for (int e2 = 0; e2 < 4; e2++) {
        int e = tid + e2 * 256;
        int row = e >> 4, c4 = e & 15;
        *reinterpret_cast<float4*>(W0 + row * 68 + c4 * 4 + ((c4 >> 3) << 2)) = g2r[e2];
        *reinterpret_cast<float4*>(W1 + row * 68 + c4 * 4 + ((c4 >> 3) << 2)) = fc2r[e2];
    }
    __syncthreads();                 // CTA-wide: g2/fc2 visible

    // ---- GEMM3: logits = a1@g2 + g2b ----
    gemmT4(Tb, W0, trr, tcoff, accA);
#pragma unroll
    for (int i = 0; i < 4; i++) {
        u0 = unpk(accA[i][0]); u1 = unpk(accA[i][1]); u2 = unpk(accA[i][2]); u3 = unpk(accA[i][3]);
        a1s[i][0] = u0.x + g2bS[c0 + 0]; a1s[i][1] = u0.y + g2bS[c0 + 1];
        a1s[i][2] = u1.x + g2bS[c0 + 2]; a1s[i][3] = u1.y + g2bS[c0 + 3];
        a1s[i][4] = u2.x + g2bS[c0 + 4]; a1s[i][5] = u2.y + g2bS[c0 + 5];
        a1s[i][6] = u3.x + g2bS[c0 + 6]; a1s[i][7] = u3.y + g2bS[c0 + 7];
    }
    BARG(gbar);                      // group-local: GEMM3 Tb reads done
#pragma unroll
    for (int i = 0; i < 4; i++) {
        int r = trr + 16 * i;
        *reinterpret_cast<float4*>(Tb + r * 68 + c0)     = make_float4(a1s[i][0], a1s[i][1], a1s[i][2], a1s[i][3]);
        *reinterpret_cast<float4*>(Tb + r * 68 + c0 + 4) = make_float4(a1s[i][4], a1s[i][5], a1s[i][6], a1s[i][7]);
    }
    BARG(gbar);                      // group-local: logits staged

    // ---- softmax over neighbors per (point, channel-pair): 8-byte LDS/STG ----
    {
        const int p = l >> 5;                   // 0..3 (point within group)
        const int f0 = (l & 31) * 2;            // channel pair
        const int pi = pbase + g * 4 + p;
        float2 z[16];
        float m0 = -3.402823e38f, m1 = -3.402823e38f;
#pragma unroll
        for (int j = 0; j < 16; j++) {
            z[j] = *reinterpret_cast<const float2*>(Tb + (p * 16 + j) * 68 + f0);
            m0 = fmaxf(m0, z[j].x); m1 = fmaxf(m1, z[j].y);
        }
        float s0 = 0.f, s1 = 0.f;
#pragma unroll
        for (int j = 0; j < 16; j++) {
            float e0 = __expf((z[j].x - m0) * 0.125f);
            float e1 = __expf((z[j].y - m1) * 0.125f);
            z[j].x = e0; z[j].y = e1; s0 += e0; s1 += e1;
        }
        float inv0 = 1.f / s0, inv1 = 1.f / s1;
        float r0a = 0.f, r1a = 0.f;
#pragma unroll
        for (int j = 0; j < 16; j++) {
            float a0 = z[j].x * inv0, a1 = z[j].y * inv1;
            *reinterpret_cast<float2*>(outAttn + ((size_t)pi * 16 + j) * 64 + f0) = make_float2(a0, a1);
            float2 vp = *reinterpret_cast<const float2*>(vpS + (p * 16 + j) * 68 + f0);
            r0a = fmaf(a0, vp.x, r0a); r1a = fmaf(a1, vp.y, r1a);
        }
        *reinterpret_cast<float2*>(resS + (g * 4 + p) * 64 + f0) = make_float2(r0a, r1a);
    }
    BARG(gbar);                      // group-local: resS staged

    // ---- out = res@fc2 + fc2b + features (fc2 from W1 smem) ----
    {
        const int f = l & 63, ph = l >> 6;
        const int fp = f + ((f >> 5) << 2);
        const int p0 = g * 4 + ph * 2;
        float o0 = fc2b[f] + features[(size_t)(pbase + p0 + 0) * 64 + f];
        float o1 = fc2b[f] + features[(size_t)(pbase + p0 + 1) * 64 + f];
#pragma unroll 8
        for (int i = 0; i < 64; i++) {
            float w = W1[i * 68 + fp];
            o0 = fmaf(resS[(p0 + 0) * 64 + i], w, o0);
            o1 = fmaf(resS[(p0 + 1) * 64 + i], w, o1);
        }
        outRes[(size_t)(pbase + p0 + 0) * 64 + f] = o0;
        outRes[(size_t)(pbase + p0 + 1) * 64 + f] = o1;
    }
}

// =========================================================================
extern "C" void kernel_launch(void* const* d_in, const int* in_sizes, int n_in,
                              void* d_out, int out_size) {
    const float* xyz      = (const float*)d_in[0];
    const float* features = (const float*)d_in[1];
    const int*   knn      = (const int*)d_in[2];
    const float* fc1w = (const float*)d_in[3];
    const float* fc1b = (const float*)d_in[4];
    const float* fc2w = (const float*)d_in[5];
    const float* fc2b = (const float*)d_in[6];
    const float* d1w  = (const float*)d_in[7];
    const float* d1b  = (const float*)d_in[8];
    const float* d2w  = (const float*)d_in[9];
    const float* d2b  = (const float*)d_in[10];
    const float* g1w  = (const float*)d_in[11];
    const float* g1b  = (const float*)d_in[12];
    const float* g2w  = (const float*)d_in[13];
    const float* g2b  = (const float*)d_in[14];
    const float* wq   = (const float*)d_in[15];
    const float* wk   = (const float*)d_in[16];
    const float* wv   = (const float*)d_in[17];

    float* outRes  = (float*)d_out;
    float* outAttn = outRes + (size_t)Mm * 64;   // tuple order: (res, attn)

    const int smem2 = 27712 * 4;   // 110848 B -> 2 CTAs/SM
    cudaFuncSetAttribute(k2_main, cudaFuncAttributeMaxDynamicSharedMemorySize, smem2);

    k0_prep<<<3, 256>>>(d2w, g1w, wq, wk, d2b, g1b);
    k1_proj<<<Mm / 64, 256>>>(features, fc1w, fc1b, wv);
    k2_main<<<Mm / 8, 256, smem2>>>(xyz, features, knn,
                                    d1w, d1b, d2w, d2b, g2w, g2b,
                                    fc2w, fc2b, outRes, outAttn);
}